// round 9
// baseline (speedup 1.0000x reference)
#include <cuda_runtime.h>
#include <math.h>

#define TT 2048
#define DD 1024
#define NT 8192
#define KTOP 4

__device__ float2 g_Qhl[NT * 32];        // [row][k] (hi,lo)
__device__ float2 g_KThl[4 * 32 * TT];   // [b][k][t] (hi,lo)

__device__ __forceinline__ float2 tf_split(float x) {
    unsigned u; asm("cvt.rna.tf32.f32 %0, %1;" : "=r"(u) : "f"(x));
    float h = __uint_as_float(u);
    return make_float2(h, x - h);
}
__device__ __forceinline__ void mma8(float* c, unsigned a0, unsigned a1,
                                     unsigned a2, unsigned a3,
                                     unsigned b0, unsigned b1) {
    asm volatile(
        "mma.sync.aligned.m16n8k8.row.col.f32.tf32.tf32.f32 "
        "{%0,%1,%2,%3}, {%4,%5,%6,%7}, {%8,%9}, {%0,%1,%2,%3};"
        : "+f"(c[0]), "+f"(c[1]), "+f"(c[2]), "+f"(c[3])
        : "r"(a0), "r"(a1), "r"(a2), "r"(a3), "r"(b0), "r"(b1));
}
__device__ __forceinline__ void mma3(float* c, const float2* a, float2 b0, float2 b1) {
    unsigned ah0 = __float_as_uint(a[0].x), ah1 = __float_as_uint(a[1].x),
             ah2 = __float_as_uint(a[2].x), ah3 = __float_as_uint(a[3].x);
    mma8(c, ah0, ah1, ah2, ah3, __float_as_uint(b0.y), __float_as_uint(b1.y));
    mma8(c, __float_as_uint(a[0].y), __float_as_uint(a[1].y),
            __float_as_uint(a[2].y), __float_as_uint(a[3].y),
            __float_as_uint(b0.x), __float_as_uint(b1.x));
    mma8(c, ah0, ah1, ah2, ah3, __float_as_uint(b0.x), __float_as_uint(b1.x));
}
__device__ __forceinline__ void upd4(float* v, int* ix, float s, int si) {
    if (s > v[3]) {
        if (s > v[1]) {
            v[3] = v[2]; ix[3] = ix[2]; v[2] = v[1]; ix[2] = ix[1];
            if (s > v[0]) { v[1] = v[0]; ix[1] = ix[0]; v[0] = s; ix[0] = si; }
            else          { v[1] = s; ix[1] = si; }
        } else {
            if (s > v[2]) { v[3] = v[2]; ix[3] = ix[2]; v[2] = s; ix[2] = si; }
            else          { v[3] = s; ix[3] = si; }
        }
    }
}

// ---------------------------------------------------------------------------
// Kernel 1: projection (tf32x3). grid=256 (32 rows/block), 256 thr.
// Warp tile: 16 rows x 16 cols (wm in {0,1}, wn in {0..3}, 2 n-tiles).
// Register-prefetched staging; writes Q row-major + K transposed, pre-split.
// ---------------------------------------------------------------------------
__global__ __launch_bounds__(256) void proj_mma(
    const float* __restrict__ x, const float* __restrict__ Wq,
    const float* __restrict__ bq, const float* __restrict__ Wk,
    const float* __restrict__ bk)
{
    __shared__ float2 Xs[32][33];   // [row][k]
    __shared__ float2 Ws[32][65];   // [k][col]
    __shared__ float  sbias[64];

    const int tid = threadIdx.x, lane = tid & 31, warp = tid >> 5;
    const int g = lane >> 2, t = lane & 3;
    const int wm = warp >> 2, wn = warp & 3;
    const int row0 = blockIdx.x * 32;

    if (tid < 64) sbias[tid] = (tid < 32) ? bq[tid] : bk[tid - 32];

    // loaders
    const int xrl = tid >> 3, xk4 = (tid & 7) * 4;          // X: row, k
    const int wcl = tid >> 2, wk8 = (tid & 3) * 8;          // W: col, k
    const float* xrow = x + (size_t)(row0 + xrl) * DD;
    const float* wrow = (wcl < 32) ? (Wq + (size_t)wcl * DD)
                                   : (Wk + (size_t)(wcl - 32) * DD);

    float4 px, pw0, pw1;
    auto ldg = [&](int kt) {
        const int kb = kt * 32;
        px  = *(const float4*)&xrow[kb + xk4];
        pw0 = *(const float4*)&wrow[kb + wk8];
        pw1 = *(const float4*)&wrow[kb + wk8 + 4];
    };
    auto sts = [&]() {
        const float* xv = (const float*)&px;
        const float* w0 = (const float*)&pw0;
        const float* w1 = (const float*)&pw1;
        #pragma unroll
        for (int i = 0; i < 4; i++) {
            Xs[xrl][xk4 + i]     = tf_split(xv[i]);
            Ws[wk8 + i][wcl]     = tf_split(w0[i]);
            Ws[wk8 + 4 + i][wcl] = tf_split(w1[i]);
        }
    };

    float acc[2][4];
    #pragma unroll
    for (int i = 0; i < 2; i++)
        #pragma unroll
        for (int j = 0; j < 4; j++) acc[i][j] = 0.0f;

    ldg(0);
    for (int kt = 0; kt < 32; kt++) {
        sts();
        __syncthreads();
        if (kt < 31) ldg(kt + 1);       // LDG in flight during compute
        #pragma unroll
        for (int k8 = 0; k8 < 4; k8++) {
            const int kk = k8 * 8;
            float2 a[4];
            a[0] = Xs[wm * 16 + g][kk + t];
            a[1] = Xs[wm * 16 + g + 8][kk + t];
            a[2] = Xs[wm * 16 + g][kk + t + 4];
            a[3] = Xs[wm * 16 + g + 8][kk + t + 4];
            #pragma unroll
            for (int nt = 0; nt < 2; nt++) {
                const int c0 = wn * 16 + nt * 8 + g;
                mma3(acc[nt], a, Ws[kk + t][c0], Ws[kk + t + 4][c0]);
            }
        }
        __syncthreads();                // before next sts overwrites
    }

    const int rA = row0 + wm * 16 + g, rB = rA + 8;
    const int bb = row0 >> 11;
    const int tA = rA & (TT - 1), tB = tA + 8;
    #pragma unroll
    for (int nt = 0; nt < 2; nt++) {
        const int c = wn * 16 + nt * 8 + 2 * t;
        #pragma unroll
        for (int h = 0; h < 2; h++) {
            const int cc = c + h;
            float2 sA = tf_split(acc[nt][h]     + sbias[cc]);
            float2 sB = tf_split(acc[nt][2 + h] + sbias[cc]);
            if (cc < 32) {
                g_Qhl[(size_t)rA * 32 + cc] = sA;
                g_Qhl[(size_t)rB * 32 + cc] = sB;
            } else {
                const int kc = cc - 32;
                g_KThl[((size_t)bb * 32 + kc) * TT + tA] = sA;
                g_KThl[((size_t)bb * 32 + kc) * TT + tB] = sB;
            }
        }
    }
}

// ---------------------------------------------------------------------------
// Kernel 2: similarity (tf32x3) + top-4 + fused gather/mean.
// grid=256 (32 rows/block), 256 thr. 32 tiles of 64 keys, register-prefetched.
// Warp tile: 16 rows x 16 keys (2 n-tiles) -> 8 upd4/thread/tile.
// ---------------------------------------------------------------------------
__global__ __launch_bounds__(256) void sim_gather(
    const float* __restrict__ x, float* __restrict__ out)
{
    __shared__ float2 Qs[32][33];
    __shared__ float2 Kt[32][66];
    __shared__ float  Mv[32][16];
    __shared__ int    Mi[32][16];
    __shared__ __align__(16) int sel[32][4];

    const int tid = threadIdx.x, lane = tid & 31, warp = tid >> 5;
    const int g = lane >> 2, t = lane & 3;
    const int wm = warp >> 2, wn = warp & 3;
    const int row0 = blockIdx.x * 32;
    const int bb   = row0 >> 11;

    {   // stage Q once
        const int r = tid >> 3, kq = (tid & 7) * 4;
        const float2* src = &g_Qhl[(size_t)(row0 + r) * 32 + kq];
        #pragma unroll
        for (int i = 0; i < 4; i++) Qs[r][kq + i] = src[i];
    }

    float tvA[4], tvB[4]; int tiA[4], tiB[4];
    #pragma unroll
    for (int p = 0; p < 4; p++) {
        tvA[p] = tvB[p] = -INFINITY; tiA[p] = tiB[p] = 0;
    }

    const float2* Kb = &g_KThl[(size_t)bb * 32 * TT];
    const int sk = tid >> 3, sj = tid & 7;    // staging: k row, float4 slot

    float4 pr[4];
    auto ldg = [&](int tile) {
        const float4* src = (const float4*)&Kb[(size_t)sk * TT + tile * 64];
        #pragma unroll
        for (int l = 0; l < 4; l++) pr[l] = src[sj + l * 8];
    };

    ldg(0);
    __syncthreads();    // Qs visible

    for (int tile = 0; tile < 32; tile++) {
        {
            float4* dst = (float4*)&Kt[sk][0];
            #pragma unroll
            for (int l = 0; l < 4; l++) dst[sj + l * 8] = pr[l];
        }
        __syncthreads();
        if (tile < 31) ldg(tile + 1);

        float acc[2][4];
        #pragma unroll
        for (int i = 0; i < 2; i++)
            #pragma unroll
            for (int j = 0; j < 4; j++) acc[i][j] = 0.0f;

        #pragma unroll
        for (int k8 = 0; k8 < 4; k8++) {
            const int kk = k8 * 8;
            float2 a[4];
            a[0] = Qs[wm * 16 + g][kk + t];
            a[1] = Qs[wm * 16 + g + 8][kk + t];
            a[2] = Qs[wm * 16 + g][kk + t + 4];
            a[3] = Qs[wm * 16 + g + 8][kk + t + 4];
            #pragma unroll
            for (int nt = 0; nt < 2; nt++) {
                const int c0 = wn * 16 + nt * 8 + g;
                mma3(acc[nt], a, Kt[kk + t][c0], Kt[kk + t + 4][c0]);
            }
        }

        #pragma unroll
        for (int nt = 0; nt < 2; nt++) {
            const int idx = tile * 64 + wn * 16 + nt * 8 + 2 * t;
            upd4(tvA, tiA, acc[nt][0], idx);
            upd4(tvA, tiA, acc[nt][1], idx + 1);
            upd4(tvB, tiB, acc[nt][2], idx);
            upd4(tvB, tiB, acc[nt][3], idx + 1);
        }
        __syncthreads();    // Kt consumed before next STS
    }

    // merge across the 4 t-lanes sharing each row (snapshot then insert)
    #pragma unroll
    for (int off = 1; off <= 2; off <<= 1) {
        float ov[4]; int oi[4];
        #pragma unroll
        for (int p = 0; p < 4; p++) {
            ov[p] = __shfl_xor_sync(0xFFFFFFFFu, tvA[p], off);
            oi[p] = __shfl_xor_sync(0xFFFFFFFFu, tiA[p], off);
        }
        #pragma unroll
        for (int p = 0; p < 4; p++) upd4(tvA, tiA, ov[p], oi[p]);
        #pragma unroll
        for (int p = 0; p < 4; p++) {
            ov[p] = __shfl_xor_sync(0xFFFFFFFFu, tvB[p], off);
            oi[p] = __shfl_xor_sync(0xFFFFFFFFu, tiB[p], off);
        }
        #pragma unroll
        for (int p = 0; p < 4; p++) upd4(tvB, tiB, ov[p], oi[p]);
    }

    if (t == 0) {
        const int rA = wm * 16 + g, rB = rA + 8;
        #pragma unroll
        for (int p = 0; p < 4; p++) {
            Mv[rA][wn * 4 + p] = tvA[p]; Mi[rA][wn * 4 + p] = tiA[p];
            Mv[rB][wn * 4 + p] = tvB[p]; Mi[rB][wn * 4 + p] = tiB[p];
        }
    }
    __syncthreads();

    if (tid < 32) {
        float cv[16]; int ci[16];
        #pragma unroll
        for (int k = 0; k < 16; k++) { cv[k] = Mv[tid][k]; ci[k] = Mi[tid][k]; }
        #pragma unroll
        for (int p = 0; p < KTOP; p++) {
            int best = 0;
            #pragma unroll
            for (int k = 1; k < 16; k++)
                if (cv[k] > cv[best]) best = k;
            sel[tid][p] = ci[best];
            cv[best] = -INFINITY;
        }
    }
    __syncthreads();

    // fused gather + mean: warp per row, 4 rows per warp
    const float4* xb4 = (const float4*)(x + (size_t)bb * TT * DD);
    float4* out4 = (float4*)out;
    #pragma unroll
    for (int rr = 0; rr < 4; rr++) {
        const int rl = warp * 4 + rr;
        int4 iv = *(const int4*)&sel[rl][0];
        const float4* n0 = xb4 + (size_t)iv.x * 256;
        const float4* n1 = xb4 + (size_t)iv.y * 256;
        const float4* n2 = xb4 + (size_t)iv.z * 256;
        const float4* n3 = xb4 + (size_t)iv.w * 256;
        float4* o4 = out4 + (size_t)(row0 + rl) * 256;
        #pragma unroll
        for (int j = 0; j < 8; j++) {
            int c = lane + j * 32;
            float4 A = n0[c], B = n1[c], C = n2[c], D = n3[c];
            float4 o;
            o.x = (A.x + B.x + C.x + D.x) * 0.25f;
            o.y = (A.y + B.y + C.y + D.y) * 0.25f;
            o.z = (A.z + B.z + C.z + D.z) * 0.25f;
            o.w = (A.w + B.w + C.w + D.w) * 0.25f;
            o4[c] = o;
        }
    }
}

// ---------------------------------------------------------------------------
extern "C" void kernel_launch(void* const* d_in, const int* in_sizes, int n_in,
                              void* d_out, int out_size)
{
    const float* x  = (const float*)d_in[0];
    const float* Wq = (const float*)d_in[1];
    const float* bq = (const float*)d_in[2];
    const float* Wk = (const float*)d_in[3];
    const float* bk = (const float*)d_in[4];
    float* out = (float*)d_out;

    proj_mma<<<256, 256>>>(x, Wq, bq, Wk, bk);
    sim_gather<<<256, 256>>>(x, out);
}

// round 10
// speedup vs baseline: 1.1012x; 1.1012x over previous
#include <cuda_runtime.h>
#include <math.h>

#define TT 2048
#define DD 1024
#define NT 8192
#define KTOP 4

__device__ float2 g_Qhl[NT * 32];   // [row][k] (hi,lo)
__device__ float2 g_Khl[NT * 32];   // [row][k] (hi,lo)

__device__ __forceinline__ float2 tf_split(float x) {
    unsigned u; asm("cvt.rna.tf32.f32 %0, %1;" : "=r"(u) : "f"(x));
    float h = __uint_as_float(u);
    return make_float2(h, x - h);
}
__device__ __forceinline__ void mma8(float* c, unsigned a0, unsigned a1,
                                     unsigned a2, unsigned a3,
                                     unsigned b0, unsigned b1) {
    asm volatile(
        "mma.sync.aligned.m16n8k8.row.col.f32.tf32.tf32.f32 "
        "{%0,%1,%2,%3}, {%4,%5,%6,%7}, {%8,%9}, {%0,%1,%2,%3};"
        : "+f"(c[0]), "+f"(c[1]), "+f"(c[2]), "+f"(c[3])
        : "r"(a0), "r"(a1), "r"(a2), "r"(a3), "r"(b0), "r"(b1));
}
__device__ __forceinline__ void mma3(float* c, const float2* a, float2 b0, float2 b1) {
    unsigned ah0 = __float_as_uint(a[0].x), ah1 = __float_as_uint(a[1].x),
             ah2 = __float_as_uint(a[2].x), ah3 = __float_as_uint(a[3].x);
    mma8(c, ah0, ah1, ah2, ah3, __float_as_uint(b0.y), __float_as_uint(b1.y));
    mma8(c, __float_as_uint(a[0].y), __float_as_uint(a[1].y),
            __float_as_uint(a[2].y), __float_as_uint(a[3].y),
            __float_as_uint(b0.x), __float_as_uint(b1.x));
    mma8(c, ah0, ah1, ah2, ah3, __float_as_uint(b0.x), __float_as_uint(b1.x));
}
__device__ __forceinline__ void upd4(float* v, int* ix, float s, int si) {
    if (s > v[3]) {
        if (s > v[1]) {
            v[3] = v[2]; ix[3] = ix[2]; v[2] = v[1]; ix[2] = ix[1];
            if (s > v[0]) { v[1] = v[0]; ix[1] = ix[0]; v[0] = s; ix[0] = si; }
            else          { v[1] = s; ix[1] = si; }
        } else {
            if (s > v[2]) { v[3] = v[2]; ix[3] = ix[2]; v[2] = s; ix[2] = si; }
            else          { v[3] = s; ix[3] = si; }
        }
    }
}

// ---------------------------------------------------------------------------
// Kernel 1: projection (tf32x3). grid=256 (32 rows/block), 256 thr.
// A = X rows (m16), B = W cols (n8). Warp: 16 rows x 16 cols. Single-sync
// double-buffered k-chunks of 32. Writes Q and K both [row][k], pre-split.
// ---------------------------------------------------------------------------
__global__ __launch_bounds__(256) void proj_mma(
    const float* __restrict__ x, const float* __restrict__ Wq,
    const float* __restrict__ bq, const float* __restrict__ Wk,
    const float* __restrict__ bk)
{
    __shared__ float2 Xs[2][32][34];   // [row][k], pad 34 (2-way max)
    __shared__ float2 Ws[2][32][66];   // [k][col], pad 66
    __shared__ float  sbias[64];

    const int tid = threadIdx.x, lane = tid & 31, warp = tid >> 5;
    const int g = lane >> 2, t = lane & 3;
    const int wm = warp >> 2, wn = warp & 3;
    const int row0 = blockIdx.x * 32;

    if (tid < 64) sbias[tid] = (tid < 32) ? bq[tid] : bk[tid - 32];

    const int xrl = tid >> 3, xk4 = (tid & 7) * 4;   // X loader: row, k
    const int wcl = tid >> 2, wk8 = (tid & 3) * 8;   // W loader: col, k
    const float* xrow = x + (size_t)(row0 + xrl) * DD;
    const float* wrow = (wcl < 32) ? (Wq + (size_t)wcl * DD)
                                   : (Wk + (size_t)(wcl - 32) * DD);

    float4 px, pw0, pw1;
    auto ldg = [&](int kt) {
        const int kb = kt * 32;
        px  = *(const float4*)&xrow[kb + xk4];
        pw0 = *(const float4*)&wrow[kb + wk8];
        pw1 = *(const float4*)&wrow[kb + wk8 + 4];
    };
    auto sts = [&](int bf) {
        const float* xv = (const float*)&px;
        const float* w0 = (const float*)&pw0;
        const float* w1 = (const float*)&pw1;
        #pragma unroll
        for (int i = 0; i < 4; i++) {
            Xs[bf][xrl][xk4 + i]     = tf_split(xv[i]);
            Ws[bf][wk8 + i][wcl]     = tf_split(w0[i]);
            Ws[bf][wk8 + 4 + i][wcl] = tf_split(w1[i]);
        }
    };

    float acc[2][4];
    #pragma unroll
    for (int i = 0; i < 2; i++)
        #pragma unroll
        for (int j = 0; j < 4; j++) acc[i][j] = 0.0f;

    ldg(0); sts(0);
    __syncthreads();

    for (int kt = 0; kt < 32; kt++) {
        const int bf = kt & 1;
        if (kt < 31) ldg(kt + 1);
        #pragma unroll
        for (int k8 = 0; k8 < 4; k8++) {
            const int kk = k8 * 8;
            float2 a[4];
            a[0] = Xs[bf][wm * 16 + g][kk + t];
            a[1] = Xs[bf][wm * 16 + g + 8][kk + t];
            a[2] = Xs[bf][wm * 16 + g][kk + t + 4];
            a[3] = Xs[bf][wm * 16 + g + 8][kk + t + 4];
            #pragma unroll
            for (int nt = 0; nt < 2; nt++) {
                const int c0 = wn * 16 + nt * 8 + g;
                mma3(acc[nt], a, Ws[bf][kk + t][c0], Ws[bf][kk + t + 4][c0]);
            }
        }
        if (kt < 31) {
            sts(bf ^ 1);
            __syncthreads();
        }
    }

    const int rA = row0 + wm * 16 + g, rB = rA + 8;
    #pragma unroll
    for (int nt = 0; nt < 2; nt++) {
        const int c = wn * 16 + nt * 8 + 2 * t;
        #pragma unroll
        for (int h = 0; h < 2; h++) {
            const int cc = c + h;
            float2 sA = tf_split(acc[nt][h]     + sbias[cc]);
            float2 sB = tf_split(acc[nt][2 + h] + sbias[cc]);
            if (cc < 32) {
                g_Qhl[(size_t)rA * 32 + cc] = sA;
                g_Qhl[(size_t)rB * 32 + cc] = sB;
            } else {
                g_Khl[(size_t)rA * 32 + cc - 32] = sA;
                g_Khl[(size_t)rB * 32 + cc - 32] = sB;
            }
        }
    }
}

// ---------------------------------------------------------------------------
// Kernel 2: similarity (tf32x3, A=keys/B=queries) + prefiltered top-4 +
// fused gather/mean. grid=256 (32 rows/block), 256 thr, 32 tiles of 64 keys.
// Warp: 8 rows (rg=warp>>1) x 32 keys (kh=warp&1), 2 mtiles of 16 keys.
// Thread: 2 query lists (cols 2t,2t+1), 4 same-row values per tile each.
// ---------------------------------------------------------------------------
__global__ __launch_bounds__(256) void sim_gather(
    const float* __restrict__ x, float* __restrict__ out)
{
    __shared__ float2 Qs[32][34];       // [row][k]
    __shared__ float2 Kt[2][64][34];    // [key][k], double-buffered
    __shared__ float  Mv[32][8];
    __shared__ int    Mi[32][8];
    __shared__ __align__(16) int sel[32][4];

    const int tid = threadIdx.x, lane = tid & 31, warp = tid >> 5;
    const int g = lane >> 2, t = lane & 3;
    const int rbase = (warp >> 1) * 8;      // row group
    const int kh    = (warp & 1) * 32;      // key half within 64-key tile
    const int row0  = blockIdx.x * 32;
    const int bb    = row0 >> 11;

    {   // stage Q once: [row][k]
        const int r = tid >> 3, kq = (tid & 7) * 4;
        const float2* src = &g_Qhl[(size_t)(row0 + r) * 32 + kq];
        #pragma unroll
        for (int i = 0; i < 4; i++) Qs[r][kq + i] = src[i];
    }

    const float2* Kb = &g_Khl[(size_t)bb * TT * 32];
    const int sk = tid >> 2, sq = (tid & 3) * 8;     // staging: key, k-offset
    float4 pr[4];
    auto ldg = [&](int tile) {
        const float4* src = (const float4*)&Kb[(size_t)(tile * 64 + sk) * 32 + sq];
        #pragma unroll
        for (int l = 0; l < 4; l++) pr[l] = src[l];
    };
    auto sts = [&](int bf) {
        float4* dst = (float4*)&Kt[bf][sk][sq];
        #pragma unroll
        for (int l = 0; l < 4; l++) dst[l] = pr[l];
    };

    float tvA[4], tvB[4]; int tiA[4], tiB[4];
    #pragma unroll
    for (int p = 0; p < 4; p++) {
        tvA[p] = tvB[p] = -INFINITY; tiA[p] = tiB[p] = 0;
    }

    ldg(0); sts(0);
    __syncthreads();

    for (int tile = 0; tile < 32; tile++) {
        const int bf = tile & 1;
        if (tile < 31) ldg(tile + 1);

        float acc[2][4];
        #pragma unroll
        for (int i = 0; i < 2; i++)
            #pragma unroll
            for (int j = 0; j < 4; j++) acc[i][j] = 0.0f;

        #pragma unroll
        for (int k8 = 0; k8 < 4; k8++) {
            const int kk = k8 * 8;
            float2 b0 = Qs[rbase + g][kk + t];      // B: queries, col=g
            float2 b1 = Qs[rbase + g][kk + t + 4];
            #pragma unroll
            for (int mt = 0; mt < 2; mt++) {
                const int kl = kh + mt * 16;
                float2 a[4];
                a[0] = Kt[bf][kl + g][kk + t];
                a[1] = Kt[bf][kl + g + 8][kk + t];
                a[2] = Kt[bf][kl + g][kk + t + 4];
                a[3] = Kt[bf][kl + g + 8][kk + t + 4];
                mma3(acc[mt], a, b0, b1);
            }
        }

        // prefiltered top-4: query A = rbase+2t gets c0,c2 of both mtiles
        const int kb0 = tile * 64 + kh + g;
        {
            float v0 = acc[0][0], v1 = acc[0][2], v2 = acc[1][0], v3 = acc[1][2];
            float m = fmaxf(fmaxf(v0, v1), fmaxf(v2, v3));
            if (m > tvA[3]) {
                upd4(tvA, tiA, v0, kb0);
                upd4(tvA, tiA, v1, kb0 + 8);
                upd4(tvA, tiA, v2, kb0 + 16);
                upd4(tvA, tiA, v3, kb0 + 24);
            }
        }
        {
            float v0 = acc[0][1], v1 = acc[0][3], v2 = acc[1][1], v3 = acc[1][3];
            float m = fmaxf(fmaxf(v0, v1), fmaxf(v2, v3));
            if (m > tvB[3]) {
                upd4(tvB, tiB, v0, kb0);
                upd4(tvB, tiB, v1, kb0 + 8);
                upd4(tvB, tiB, v2, kb0 + 16);
                upd4(tvB, tiB, v3, kb0 + 24);
            }
        }

        if (tile < 31) {
            sts(bf ^ 1);
            __syncthreads();
        }
    }

    // merge across g-lanes (same t): xor 4,8,16; snapshot then insert
    #pragma unroll
    for (int off = 4; off <= 16; off <<= 1) {
        float ov[4]; int oi[4];
        #pragma unroll
        for (int p = 0; p < 4; p++) {
            ov[p] = __shfl_xor_sync(0xFFFFFFFFu, tvA[p], off);
            oi[p] = __shfl_xor_sync(0xFFFFFFFFu, tiA[p], off);
        }
        #pragma unroll
        for (int p = 0; p < 4; p++) upd4(tvA, tiA, ov[p], oi[p]);
        #pragma unroll
        for (int p = 0; p < 4; p++) {
            ov[p] = __shfl_xor_sync(0xFFFFFFFFu, tvB[p], off);
            oi[p] = __shfl_xor_sync(0xFFFFFFFFu, tiB[p], off);
        }
        #pragma unroll
        for (int p = 0; p < 4; p++) upd4(tvB, tiB, ov[p], oi[p]);
    }

    if (g == 0) {
        const int kcol = (warp & 1) * 4;
        #pragma unroll
        for (int p = 0; p < 4; p++) {
            Mv[rbase + 2 * t][kcol + p]     = tvA[p];
            Mi[rbase + 2 * t][kcol + p]     = tiA[p];
            Mv[rbase + 2 * t + 1][kcol + p] = tvB[p];
            Mi[rbase + 2 * t + 1][kcol + p] = tiB[p];
        }
    }
    __syncthreads();

    if (tid < 32) {
        float cv[8]; int ci[8];
        #pragma unroll
        for (int k = 0; k < 8; k++) { cv[k] = Mv[tid][k]; ci[k] = Mi[tid][k]; }
        #pragma unroll
        for (int p = 0; p < KTOP; p++) {
            int best = 0;
            #pragma unroll
            for (int k = 1; k < 8; k++)
                if (cv[k] > cv[best]) best = k;
            sel[tid][p] = ci[best];
            cv[best] = -INFINITY;
        }
    }
    __syncthreads();

    // fused gather + mean: warp per row, 4 rows per warp
    const float4* xb4 = (const float4*)(x + (size_t)bb * TT * DD);
    float4* out4 = (float4*)out;
    #pragma unroll
    for (int rr = 0; rr < 4; rr++) {
        const int rl = warp * 4 + rr;
        int4 iv = *(const int4*)&sel[rl][0];
        const float4* n0 = xb4 + (size_t)iv.x * 256;
        const float4* n1 = xb4 + (size_t)iv.y * 256;
        const float4* n2 = xb4 + (size_t)iv.z * 256;
        const float4* n3 = xb4 + (size_t)iv.w * 256;
        float4* o4 = out4 + (size_t)(row0 + rl) * 256;
        #pragma unroll
        for (int j = 0; j < 8; j++) {
            int c = lane + j * 32;
            float4 A = n0[c], B = n1[c], C = n2[c], D = n3[c];
            float4 o;
            o.x = (A.x + B.x + C.x + D.x) * 0.25f;
            o.y = (A.y + B.y + C.y + D.y) * 0.25f;
            o.z = (A.z + B.z + C.z + D.z) * 0.25f;
            o.w = (A.w + B.w + C.w + D.w) * 0.25f;
            o4[c] = o;
        }
    }
}

// ---------------------------------------------------------------------------
extern "C" void kernel_launch(void* const* d_in, const int* in_sizes, int n_in,
                              void* d_out, int out_size)
{
    const float* x  = (const float*)d_in[0];
    const float* Wq = (const float*)d_in[1];
    const float* bq = (const float*)d_in[2];
    const float* Wk = (const float*)d_in[3];
    const float* bk = (const float*)d_in[4];
    float* out = (float*)d_out;

    proj_mma<<<256, 256>>>(x, Wq, bq, Wk, bk);
    sim_gather<<<256, 256>>>(x, out);
}

// round 11
// speedup vs baseline: 1.2343x; 1.1209x over previous
#include <cuda_runtime.h>
#include <math.h>

#define TT 2048
#define DD 1024
#define NT 8192
#define KTOP 4

__device__ float2 g_Qhl[NT * 32];   // [row][k] (hi,lo)
__device__ float2 g_Khl[NT * 32];   // [row][k] (hi,lo)

__device__ __forceinline__ float2 tf_split(float x) {
    unsigned u; asm("cvt.rna.tf32.f32 %0, %1;" : "=r"(u) : "f"(x));
    float h = __uint_as_float(u);
    return make_float2(h, x - h);
}
__device__ __forceinline__ void mma8(float* c, unsigned a0, unsigned a1,
                                     unsigned a2, unsigned a3,
                                     unsigned b0, unsigned b1) {
    asm volatile(
        "mma.sync.aligned.m16n8k8.row.col.f32.tf32.tf32.f32 "
        "{%0,%1,%2,%3}, {%4,%5,%6,%7}, {%8,%9}, {%0,%1,%2,%3};"
        : "+f"(c[0]), "+f"(c[1]), "+f"(c[2]), "+f"(c[3])
        : "r"(a0), "r"(a1), "r"(a2), "r"(a3), "r"(b0), "r"(b1));
}
// a: a0=(A[g][t]) a1=(A[g+8][t]) a2=(A[g][t+4]) a3=(A[g+8][t+4]), packed (hi,lo)
__device__ __forceinline__ void mma3(float* c, float2 a0, float2 a1, float2 a2,
                                     float2 a3, float2 b0, float2 b1) {
    unsigned ah0 = __float_as_uint(a0.x), ah1 = __float_as_uint(a1.x),
             ah2 = __float_as_uint(a2.x), ah3 = __float_as_uint(a3.x);
    mma8(c, ah0, ah1, ah2, ah3, __float_as_uint(b0.y), __float_as_uint(b1.y));
    mma8(c, __float_as_uint(a0.y), __float_as_uint(a1.y),
            __float_as_uint(a2.y), __float_as_uint(a3.y),
            __float_as_uint(b0.x), __float_as_uint(b1.x));
    mma8(c, ah0, ah1, ah2, ah3, __float_as_uint(b0.x), __float_as_uint(b1.x));
}
__device__ __forceinline__ void upd4(float* v, int* ix, float s, int si) {
    if (s > v[3]) {
        if (s > v[1]) {
            v[3] = v[2]; ix[3] = ix[2]; v[2] = v[1]; ix[2] = ix[1];
            if (s > v[0]) { v[1] = v[0]; ix[1] = ix[0]; v[0] = s; ix[0] = si; }
            else          { v[1] = s; ix[1] = si; }
        } else {
            if (s > v[2]) { v[3] = v[2]; ix[3] = ix[2]; v[2] = s; ix[2] = si; }
            else          { v[3] = s; ix[3] = si; }
        }
    }
}

// ---------------------------------------------------------------------------
// Kernel 1: projection (tf32x3). grid=256 (32 rows/block), 256 thr.
// Paired-k layout: float4 = (hi_k, lo_k, hi_{k+4}, lo_{k+4}).
// Xp[row][k8*4+t], Wp[k8*4+t][col]. Fragment pair = one LDS.128.
// ---------------------------------------------------------------------------
__global__ __launch_bounds__(256) void proj_mma(
    const float* __restrict__ x, const float* __restrict__ Wq,
    const float* __restrict__ bq, const float* __restrict__ Wk,
    const float* __restrict__ bk)
{
    __shared__ float4 Xp[2][32][17];   // [row][j]
    __shared__ float4 Wp[2][16][65];   // [j][col]
    __shared__ float  sbias[64];

    const int tid = threadIdx.x, lane = tid & 31, warp = tid >> 5;
    const int g = lane >> 2, t = lane & 3;
    const int wm = warp >> 2, wn = warp & 3;
    const int row0 = blockIdx.x * 32;

    if (tid < 64) sbias[tid] = (tid < 32) ? bq[tid] : bk[tid - 32];

    // loaders: unit = (row-or-col, k8), 8 consecutive k each
    const int xrl = tid >> 2, xk8 = tid & 3;          // X: threads 0..127
    const int wcl = tid >> 2, wk8 = tid & 3;          // W: all 256
    const float* xrow = x + (size_t)(row0 + (xrl & 31)) * DD;
    const float* wrow = (wcl < 32) ? (Wq + (size_t)wcl * DD)
                                   : (Wk + (size_t)(wcl - 32) * DD);

    float4 pw0, pw1, px0, px1;
    auto ldg = [&](int kt) {
        const int kb = kt * 32;
        pw0 = *(const float4*)&wrow[kb + wk8 * 8];
        pw1 = *(const float4*)&wrow[kb + wk8 * 8 + 4];
        if (tid < 128) {
            px0 = *(const float4*)&xrow[kb + xk8 * 8];
            px1 = *(const float4*)&xrow[kb + xk8 * 8 + 4];
        }
    };
    auto sts = [&](int bf) {
        const float* w0 = (const float*)&pw0;
        const float* w1 = (const float*)&pw1;
        #pragma unroll
        for (int i = 0; i < 4; i++) {
            float2 lo = tf_split(w0[i]), hi4 = tf_split(w1[i]);
            Wp[bf][wk8 * 4 + i][wcl] = make_float4(lo.x, lo.y, hi4.x, hi4.y);
        }
        if (tid < 128) {
            const float* x0 = (const float*)&px0;
            const float* x1 = (const float*)&px1;
            #pragma unroll
            for (int i = 0; i < 4; i++) {
                float2 lo = tf_split(x0[i]), hi4 = tf_split(x1[i]);
                Xp[bf][xrl][xk8 * 4 + i] = make_float4(lo.x, lo.y, hi4.x, hi4.y);
            }
        }
    };

    float acc[2][4];
    #pragma unroll
    for (int i = 0; i < 2; i++)
        #pragma unroll
        for (int j = 0; j < 4; j++) acc[i][j] = 0.0f;

    ldg(0); sts(0);
    __syncthreads();

    for (int kt = 0; kt < 32; kt++) {
        const int bf = kt & 1;
        if (kt < 31) ldg(kt + 1);
        #pragma unroll
        for (int k8 = 0; k8 < 4; k8++) {
            const int j = k8 * 4 + t;
            float4 av0 = Xp[bf][wm * 16 + g][j];      // a0,a2
            float4 av1 = Xp[bf][wm * 16 + g + 8][j];  // a1,a3
            #pragma unroll
            for (int nt = 0; nt < 2; nt++) {
                float4 bv = Wp[bf][j][wn * 16 + nt * 8 + g];
                mma3(acc[nt],
                     make_float2(av0.x, av0.y), make_float2(av1.x, av1.y),
                     make_float2(av0.z, av0.w), make_float2(av1.z, av1.w),
                     make_float2(bv.x, bv.y),   make_float2(bv.z, bv.w));
            }
        }
        if (kt < 31) {
            sts(bf ^ 1);
            __syncthreads();
        }
    }

    const int rA = row0 + wm * 16 + g, rB = rA + 8;
    #pragma unroll
    for (int nt = 0; nt < 2; nt++) {
        const int c = wn * 16 + nt * 8 + 2 * t;
        #pragma unroll
        for (int h = 0; h < 2; h++) {
            const int cc = c + h;
            float2 sA = tf_split(acc[nt][h]     + sbias[cc]);
            float2 sB = tf_split(acc[nt][2 + h] + sbias[cc]);
            if (cc < 32) {
                g_Qhl[(size_t)rA * 32 + cc] = sA;
                g_Qhl[(size_t)rB * 32 + cc] = sB;
            } else {
                g_Khl[(size_t)rA * 32 + cc - 32] = sA;
                g_Khl[(size_t)rB * 32 + cc - 32] = sB;
            }
        }
    }
}

// ---------------------------------------------------------------------------
// Kernel 2: similarity (A=keys, B=queries in REGISTERS) + top-4 + gather.
// grid=256 (32 rows/block), 256 thr, 32 tiles of 64 keys.
// K staged in paired-k float4 layout; 16 LDS.128/thread/tile, Q zero LDS.
// ---------------------------------------------------------------------------
__global__ __launch_bounds__(256) void sim_gather(
    const float* __restrict__ x, float* __restrict__ out)
{
    __shared__ float4 Kt[2][64][17];    // [key][j] paired
    __shared__ float  Mv[32][8];
    __shared__ int    Mi[32][8];
    __shared__ __align__(16) int sel[32][4];

    const int tid = threadIdx.x, lane = tid & 31, warp = tid >> 5;
    const int g = lane >> 2, t = lane & 3;
    const int rbase = (warp >> 1) * 8;
    const int kh    = (warp & 1) * 32;
    const int row0  = blockIdx.x * 32;
    const int bb    = row0 >> 11;

    // query B-fragments in registers (tile-invariant): b0=Q[q][kk+t], b1=Q[q][kk+t+4]
    float2 bq0[4], bq1[4];
    {
        const float2* qrow = &g_Qhl[(size_t)(row0 + rbase + g) * 32];
        #pragma unroll
        for (int k8 = 0; k8 < 4; k8++) {
            bq0[k8] = qrow[k8 * 8 + t];
            bq1[k8] = qrow[k8 * 8 + t + 4];
        }
    }

    // staging: unit = (key, k8) -> 4 LDG.128 in, 4 paired STS.128 out
    const float2* Kb = &g_Khl[(size_t)bb * TT * 32];
    const int sk = tid >> 2, sk8 = tid & 3;
    float4 pr[4];
    auto ldg = [&](int tile) {
        const float4* src =
            (const float4*)&Kb[(size_t)(tile * 64 + sk) * 32 + sk8 * 8];
        #pragma unroll
        for (int l = 0; l < 4; l++) pr[l] = src[l];
    };
    auto sts = [&](int bf) {
        // pr[0..1] = k..k+3 (hi,lo), pr[2..3] = k+4..k+7
        Kt[bf][sk][sk8 * 4 + 0] = make_float4(pr[0].x, pr[0].y, pr[2].x, pr[2].y);
        Kt[bf][sk][sk8 * 4 + 1] = make_float4(pr[0].z, pr[0].w, pr[2].z, pr[2].w);
        Kt[bf][sk][sk8 * 4 + 2] = make_float4(pr[1].x, pr[1].y, pr[3].x, pr[3].y);
        Kt[bf][sk][sk8 * 4 + 3] = make_float4(pr[1].z, pr[1].w, pr[3].z, pr[3].w);
    };

    float tvA[4], tvB[4]; int tiA[4], tiB[4];
    #pragma unroll
    for (int p = 0; p < 4; p++) {
        tvA[p] = tvB[p] = -INFINITY; tiA[p] = tiB[p] = 0;
    }

    ldg(0); sts(0);
    __syncthreads();

    for (int tile = 0; tile < 32; tile++) {
        const int bf = tile & 1;
        if (tile < 31) ldg(tile + 1);

        float acc[2][4];
        #pragma unroll
        for (int i = 0; i < 2; i++)
            #pragma unroll
            for (int j = 0; j < 4; j++) acc[i][j] = 0.0f;

        #pragma unroll
        for (int k8 = 0; k8 < 4; k8++) {
            const int j = k8 * 4 + t;
            #pragma unroll
            for (int mt = 0; mt < 2; mt++) {
                const int kl = kh + mt * 16;
                float4 av0 = Kt[bf][kl + g][j];
                float4 av1 = Kt[bf][kl + g + 8][j];
                mma3(acc[mt],
                     make_float2(av0.x, av0.y), make_float2(av1.x, av1.y),
                     make_float2(av0.z, av0.w), make_float2(av1.z, av1.w),
                     bq0[k8], bq1[k8]);
            }
        }

        // prefiltered top-4 (c0,c2 -> query 2t; c1,c3 -> query 2t+1)
        const int kb0 = tile * 64 + kh + g;
        {
            float v0 = acc[0][0], v1 = acc[0][2], v2 = acc[1][0], v3 = acc[1][2];
            float m = fmaxf(fmaxf(v0, v1), fmaxf(v2, v3));
            if (m > tvA[3]) {
                upd4(tvA, tiA, v0, kb0);
                upd4(tvA, tiA, v1, kb0 + 8);
                upd4(tvA, tiA, v2, kb0 + 16);
                upd4(tvA, tiA, v3, kb0 + 24);
            }
        }
        {
            float v0 = acc[0][1], v1 = acc[0][3], v2 = acc[1][1], v3 = acc[1][3];
            float m = fmaxf(fmaxf(v0, v1), fmaxf(v2, v3));
            if (m > tvB[3]) {
                upd4(tvB, tiB, v0, kb0);
                upd4(tvB, tiB, v1, kb0 + 8);
                upd4(tvB, tiB, v2, kb0 + 16);
                upd4(tvB, tiB, v3, kb0 + 24);
            }
        }

        if (tile < 31) {
            sts(bf ^ 1);
            __syncthreads();
        }
    }

    // merge across g-lanes (xor 4,8,16), snapshot then insert
    #pragma unroll
    for (int off = 4; off <= 16; off <<= 1) {
        float ov[4]; int oi[4];
        #pragma unroll
        for (int p = 0; p < 4; p++) {
            ov[p] = __shfl_xor_sync(0xFFFFFFFFu, tvA[p], off);
            oi[p] = __shfl_xor_sync(0xFFFFFFFFu, tiA[p], off);
        }
        #pragma unroll
        for (int p = 0; p < 4; p++) upd4(tvA, tiA, ov[p], oi[p]);
        #pragma unroll
        for (int p = 0; p < 4; p++) {
            ov[p] = __shfl_xor_sync(0xFFFFFFFFu, tvB[p], off);
            oi[p] = __shfl_xor_sync(0xFFFFFFFFu, tiB[p], off);
        }
        #pragma unroll
        for (int p = 0; p < 4; p++) upd4(tvB, tiB, ov[p], oi[p]);
    }

    if (g == 0) {
        const int kcol = (warp & 1) * 4;
        #pragma unroll
        for (int p = 0; p < 4; p++) {
            Mv[rbase + 2 * t][kcol + p]     = tvA[p];
            Mi[rbase + 2 * t][kcol + p]     = tiA[p];
            Mv[rbase + 2 * t + 1][kcol + p] = tvB[p];
            Mi[rbase + 2 * t + 1][kcol + p] = tiB[p];
        }
    }
    __syncthreads();

    if (tid < 32) {
        float cv[8]; int ci[8];
        #pragma unroll
        for (int k = 0; k < 8; k++) { cv[k] = Mv[tid][k]; ci[k] = Mi[tid][k]; }
        #pragma unroll
        for (int p = 0; p < KTOP; p++) {
            int best = 0;
            #pragma unroll
            for (int k = 1; k < 8; k++)
                if (cv[k] > cv[best]) best = k;
            sel[tid][p] = ci[best];
            cv[best] = -INFINITY;
        }
    }
    __syncthreads();

    // fused gather + mean: warp per row, 4 rows per warp
    const float4* xb4 = (const float4*)(x + (size_t)bb * TT * DD);
    float4* out4 = (float4*)out;
    #pragma unroll
    for (int rr = 0; rr < 4; rr++) {
        const int rl = warp * 4 + rr;
        int4 iv = *(const int4*)&sel[rl][0];
        const float4* n0 = xb4 + (size_t)iv.x * 256;
        const float4* n1 = xb4 + (size_t)iv.y * 256;
        const float4* n2 = xb4 + (size_t)iv.z * 256;
        const float4* n3 = xb4 + (size_t)iv.w * 256;
        float4* o4 = out4 + (size_t)(row0 + rl) * 256;
        #pragma unroll
        for (int j = 0; j < 8; j++) {
            int c = lane + j * 32;
            float4 A = n0[c], B = n1[c], C = n2[c], D = n3[c];
            float4 o;
            o.x = (A.x + B.x + C.x + D.x) * 0.25f;
            o.y = (A.y + B.y + C.y + D.y) * 0.25f;
            o.z = (A.z + B.z + C.z + D.z) * 0.25f;
            o.w = (A.w + B.w + C.w + D.w) * 0.25f;
            o4[c] = o;
        }
    }
}

// ---------------------------------------------------------------------------
extern "C" void kernel_launch(void* const* d_in, const int* in_sizes, int n_in,
                              void* d_out, int out_size)
{
    const float* x  = (const float*)d_in[0];
    const float* Wq = (const float*)d_in[1];
    const float* bq = (const float*)d_in[2];
    const float* Wk = (const float*)d_in[3];
    const float* bk = (const float*)d_in[4];
    float* out = (float*)d_out;

    proj_mma<<<256, 256>>>(x, Wq, bq, Wk, bk);
    sim_gather<<<256, 256>>>(x, out);
}